// round 13
// baseline (speedup 1.0000x reference)
#include <cuda_runtime.h>
#include <cuda_fp16.h>
#include <math.h>
#include <stdint.h>

// ---------------------------------------------------------------------------
// Mamba2 block, B=2, T=1024, D_MODEL=2048, D_STATE=64, HEADDIM=64
// R12: GEMMs via fp16 mma.sync.m16n8k16 (f32 accum) — same 11-bit significand
// as the proven tf32 pipeline (rel_err 4.7e-4). Exact-fp32 dt side-channel.
// Probe/fixup net: sampled outputs checked vs fp32 dot; fp32 FFMA GEMM
// recomputes on mismatch. Scan: FFMA2 with 4-way split accumulator.
// ---------------------------------------------------------------------------

#define B_     2
#define T_     1024
#define DM     2048
#define DIN    4096
#define DCONV  4224
#define DPROJ  8384
#define NH     64
#define NTOK   (B_ * T_)   // 2048

__device__ float g_u  [(size_t)NTOK * DM];
__device__ float g_zx [(size_t)NTOK * DPROJ];
__device__ float g_xbc[(size_t)NTOK * DCONV];
__device__ float g_dt [(size_t)NTOK * NH];
__device__ float g_dA [(size_t)NTOK * NH];
__device__ float g_y  [(size_t)NTOK * DIN];
__device__ int   g_flag1, g_flag2;

// fp16 operands
__device__ __half g_uh [(size_t)NTOK * DM];
__device__ __half g_w1h[(size_t)DPROJ * DM];
__device__ __half g_yh [(size_t)NTOK * DIN];
__device__ __half g_w2h[(size_t)DM * DIN];

__device__ __forceinline__ float sigmoidf_(float v) { return 1.f / (1.f + expf(-v)); }

__device__ __forceinline__ uint32_t smem_u32(const void* p) {
    return (uint32_t)__cvta_generic_to_shared(p);
}
#define CPA16(dst, src) asm volatile("cp.async.cg.shared.global [%0], [%1], 16;" :: "r"(dst), "l"(src))
#define CPA_COMMIT()    asm volatile("cp.async.commit_group;")

// fp16 mma, fp32 accumulator
#define MMA16(d, a, b0v, b1v) asm volatile( \
    "mma.sync.aligned.m16n8k16.row.col.f32.f16.f16.f32 " \
    "{%0,%1,%2,%3},{%4,%5,%6,%7},{%8,%9},{%0,%1,%2,%3};" \
    : "+f"((d)[0]), "+f"((d)[1]), "+f"((d)[2]), "+f"((d)[3]) \
    : "r"((a)[0]), "r"((a)[1]), "r"((a)[2]), "r"((a)[3]), "r"(b0v), "r"(b1v))

// packed f32x2 helpers (scan)
#define FMAF2(d, a, b, c) \
    asm("fma.rn.f32x2 %0, %1, %2, %3;" : "=l"(d) : "l"(a), "l"(b), "l"(c))
#define MULF2(d, a, b) \
    asm("mul.rn.f32x2 %0, %1, %2;" : "=l"(d) : "l"(a), "l"(b))
__device__ __forceinline__ unsigned long long packdup(float x) {
    unsigned long long r;
    uint32_t xi = __float_as_uint(x);
    asm("mov.b64 %0, {%1,%1};" : "=l"(r) : "r"(xi));
    return r;
}
__device__ __forceinline__ float2 unpack2(unsigned long long v) {
    uint32_t lo, hi;
    asm("mov.b64 {%0,%1}, %2;" : "=r"(lo), "=r"(hi) : "l"(v));
    return make_float2(__uint_as_float(lo), __uint_as_float(hi));
}

// ---------------------------------------------------------------------------
// Weight fp32 -> fp16
// ---------------------------------------------------------------------------
__global__ void wcvt_kernel(const float* __restrict__ W,
                            __half* __restrict__ H, int n4) {
    int i = blockIdx.x * blockDim.x + threadIdx.x;
    if (i >= n4) return;
    float4 v = reinterpret_cast<const float4*>(W)[i];
    reinterpret_cast<__half2*>(H)[i * 2 + 0] = __floats2half2_rn(v.x, v.y);
    reinterpret_cast<__half2*>(H)[i * 2 + 1] = __floats2half2_rn(v.z, v.w);
}

// ---------------------------------------------------------------------------
// LayerNorm + fp16 copy of u. One block per token row.
// ---------------------------------------------------------------------------
__global__ void ln_kernel(const float* __restrict__ x,
                          const float* __restrict__ w,
                          const float* __restrict__ bb) {
    int r = blockIdx.x;
    const float* xr = x + (size_t)r * DM;
    float s = 0.f, s2 = 0.f;
    for (int i = threadIdx.x; i < DM; i += blockDim.x) {
        float v = xr[i]; s += v; s2 += v * v;
    }
    __shared__ float shs[32], shs2[32];
    int lane = threadIdx.x & 31, wid = threadIdx.x >> 5;
#pragma unroll
    for (int o = 16; o; o >>= 1) {
        s  += __shfl_xor_sync(0xffffffffu, s, o);
        s2 += __shfl_xor_sync(0xffffffffu, s2, o);
    }
    if (lane == 0) { shs[wid] = s; shs2[wid] = s2; }
    __syncthreads();
    __shared__ float mu_s, inv_s;
    if (threadIdx.x == 0) {
        float ts = 0.f, ts2 = 0.f;
        int nw = blockDim.x >> 5;
        for (int i = 0; i < nw; i++) { ts += shs[i]; ts2 += shs2[i]; }
        float mu = ts / DM;
        mu_s = mu;
        inv_s = rsqrtf(ts2 / DM - mu * mu + 1e-5f);
    }
    __syncthreads();
    float mu = mu_s, inv = inv_s;
    for (int i = threadIdx.x; i < DM; i += blockDim.x) {
        float v = (xr[i] - mu) * inv * w[i] + bb[i];
        size_t idx = (size_t)r * DM + i;
        g_u[idx]  = v;
        g_uh[idx] = __float2half_rn(v);
    }
}

// ---------------------------------------------------------------------------
// fp16 tensor-core GEMM NT: C[m,n] = sum_k A[m,k]*Bw[n,k] (+Res)
// 128x128x32 tile, 256 thr, warp tile 32x64 (2 m-frags x 8 n-frags).
// smem pitch 40 halves (80B): fragment LDS banks (20*g + tig) mod 32 distinct.
// Double-buffered cp.async; 40960B static smem.
// ---------------------------------------------------------------------------
#define HP 40   // half pitch
template<bool GUARD_N, bool RES>
__device__ __forceinline__ void gemm_f16_body(const __half* __restrict__ A,
                                              const __half* __restrict__ Bw,
                                              const float* __restrict__ Res,
                                              float* __restrict__ C,
                                              int N, int K) {
    __shared__ __align__(16) __half sm[2][2][128 * HP];  // [buf][A/B]

    const int tid  = threadIdx.x;
    const int lane = tid & 31;
    const int wid  = tid >> 5;
    const int g    = lane >> 2;
    const int tig  = lane & 3;
    const int wm0  = (wid & 3) * 32;
    const int wn0  = (wid >> 2) * 64;
    const int m0   = blockIdx.y * 128;
    const int n0   = blockIdx.x * 128;

    float acc[2][8][4];
#pragma unroll
    for (int i = 0; i < 2; i++)
#pragma unroll
        for (int j = 0; j < 8; j++)
#pragma unroll
            for (int q = 0; q < 4; q++) acc[i][j][q] = 0.f;

    auto load_tile = [&](int buf, int kc) {
#pragma unroll
        for (int i = 0; i < 2; i++) {       // A: 512 x 16B
            int id = tid + 256 * i;
            int row = id >> 2, c = id & 3;  // 4 x 16B per 64B row
            const void* src = A + (size_t)(m0 + row) * K + kc * 32 + c * 8;
            CPA16(smem_u32(&sm[buf][0][row * HP + c * 8]), src);
        }
#pragma unroll
        for (int i = 0; i < 2; i++) {       // B
            int id = tid + 256 * i;
            int row = id >> 2, c = id & 3;
            int br = n0 + row;
            if (GUARD_N && br >= N) br = N - 1;   // clamp; stores guarded
            const void* src = Bw + (size_t)br * K + kc * 32 + c * 8;
            CPA16(smem_u32(&sm[buf][1][row * HP + c * 8]), src);
        }
        CPA_COMMIT();
    };

    const int NT = K >> 5;
    load_tile(0, 0);

    for (int kt = 0; kt < NT; kt++) {
        int cur = kt & 1;
        asm volatile("cp.async.wait_group 0;");
        __syncthreads();
        if (kt + 1 < NT) load_tile(cur ^ 1, kt + 1);

        const __half* Ac = sm[cur][0];
        const __half* Bc = sm[cur][1];
#pragma unroll
        for (int s = 0; s < 2; s++) {
            int kb = s * 16;
            uint32_t a[2][4];
#pragma unroll
            for (int i = 0; i < 2; i++) {
                const __half* p = &Ac[(wm0 + 16 * i + g) * HP + kb + 2 * tig];
                a[i][0] = *(const uint32_t*)p;
                a[i][1] = *(const uint32_t*)(p + 8 * HP);
                a[i][2] = *(const uint32_t*)(p + 8);
                a[i][3] = *(const uint32_t*)(p + 8 * HP + 8);
            }
#pragma unroll
            for (int j = 0; j < 8; j++) {
                const __half* q = &Bc[(wn0 + 8 * j + g) * HP + kb + 2 * tig];
                uint32_t b0 = *(const uint32_t*)q;
                uint32_t b1 = *(const uint32_t*)(q + 8);
                MMA16(acc[0][j], a[0], b0, b1);
                MMA16(acc[1][j], a[1], b0, b1);
            }
        }
    }

    // epilogue: c0,c1 -> (row g, cols 2tig..+1); c2,c3 -> row g+8
#pragma unroll
    for (int i = 0; i < 2; i++) {
        int m = m0 + wm0 + 16 * i + g;
#pragma unroll
        for (int j = 0; j < 8; j++) {
            int n = n0 + wn0 + 8 * j + 2 * tig;
            if (GUARD_N && n >= N) continue;      // N even, float2 safe
            float2 v0 = make_float2(acc[i][j][0], acc[i][j][1]);
            float2 v1 = make_float2(acc[i][j][2], acc[i][j][3]);
            if (RES) {
                float2 r0 = *(const float2*)&Res[(size_t)m * N + n];
                float2 r1 = *(const float2*)&Res[(size_t)(m + 8) * N + n];
                v0.x += r0.x; v0.y += r0.y;
                v1.x += r1.x; v1.y += r1.y;
            }
            *(float2*)&C[(size_t)m * N + n]       = v0;
            *(float2*)&C[(size_t)(m + 8) * N + n] = v1;
        }
    }
}

__global__ __launch_bounds__(256, 2)
void gemm1_f16() {
    gemm_f16_body<true, false>(g_uh, g_w1h, nullptr, g_zx, DPROJ, DM);
}
__global__ __launch_bounds__(256, 2)
void gemm2_f16(const float* __restrict__ Res, float* __restrict__ out) {
    gemm_f16_body<false, true>(g_yh, g_w2h, Res, out, DM, DIN);
}

// ---------------------------------------------------------------------------
// Probe + fixup machinery (deterministic; re-derived every call)
// ---------------------------------------------------------------------------
#define NPROBE 64
__global__ void preclear1_kernel() {
    int s = threadIdx.x;
    if (s == 0) g_flag1 = 0;
    if (s < NPROBE) {
        int m = (s * 997) % NTOK, n = (s * 5003) % DPROJ;
        g_zx[(size_t)m * DPROJ + n] = 0.f;
    }
}
__global__ void probe1_kernel(const float* __restrict__ W) {
    __shared__ float sred[256];
    int s = blockIdx.x;
    int m = (s * 997) % NTOK, n = (s * 5003) % DPROJ;
    const float* ur = g_u + (size_t)m * DM;
    const float* wr = W + (size_t)n * DM;
    float acc = 0.f;
    for (int k = threadIdx.x; k < DM; k += 256) acc += ur[k] * wr[k];
    sred[threadIdx.x] = acc; __syncthreads();
    for (int o = 128; o; o >>= 1) {
        if (threadIdx.x < o) sred[threadIdx.x] += sred[threadIdx.x + o];
        __syncthreads();
    }
    if (threadIdx.x == 0) {
        float got = g_zx[(size_t)m * DPROJ + n];
        if (fabsf(got - sred[0]) > 0.03f) atomicExch(&g_flag1, 1);
    }
}
__global__ void preclear2_kernel(float* __restrict__ out) {
    int s = threadIdx.x;
    if (s == 0) g_flag2 = 0;
    if (s < NPROBE) {
        int m = (s * 997) % NTOK, n = (s * 131) % DM;
        out[(size_t)m * DM + n] = 0.f;
    }
}
__global__ void probe2_kernel(const float* __restrict__ x,
                              const float* __restrict__ W2,
                              const float* __restrict__ out) {
    __shared__ float sred[256];
    int s = blockIdx.x;
    int m = (s * 997) % NTOK, n = (s * 131) % DM;
    const float* yr = g_y + (size_t)m * DIN;
    const float* wr = W2 + (size_t)n * DIN;
    float acc = 0.f;
    for (int k = threadIdx.x; k < DIN; k += 256) acc += yr[k] * wr[k];
    sred[threadIdx.x] = acc; __syncthreads();
    for (int o = 128; o; o >>= 1) {
        if (threadIdx.x < o) sred[threadIdx.x] += sred[threadIdx.x + o];
        __syncthreads();
    }
    if (threadIdx.x == 0) {
        float truth = sred[0] + x[(size_t)m * DM + n];
        if (fabsf(out[(size_t)m * DM + n] - truth) > 0.03f) atomicExch(&g_flag2, 1);
    }
}

// fp32 FFMA fixup GEMM (R2-proven), early-exit on healthy flag
template<bool GUARD_N, bool RES>
__device__ __forceinline__ void sgemm_f32_body(const float* __restrict__ A,
                                               const float* __restrict__ Bw,
                                               const float* __restrict__ Res,
                                               float* __restrict__ C,
                                               int N, int K) {
    __shared__ __align__(16) float As[8][128];
    __shared__ __align__(16) float Bs[8][128];

    const int tid = threadIdx.x;
    const int m0 = blockIdx.y * 128;
    const int n0 = blockIdx.x * 128;
    const int lrow = tid >> 1;
    const int lcol = (tid & 1) << 2;
    const int tx = tid & 15;
    const int ty = tid >> 4;

    float acc[8][8];
#pragma unroll
    for (int i = 0; i < 8; i++)
#pragma unroll
        for (int j = 0; j < 8; j++) acc[i][j] = 0.f;

    int brow = n0 + lrow;
    bool bval = true;
    if (GUARD_N && brow >= N) { brow = 0; bval = false; }

    const float* Ap = A  + (size_t)(m0 + lrow) * K + lcol;
    const float* Bp = Bw + (size_t)brow * K + lcol;

    for (int k0 = 0; k0 < K; k0 += 8) {
        float4 av = *reinterpret_cast<const float4*>(Ap + k0);
        float4 bv = *reinterpret_cast<const float4*>(Bp + k0);
        if (GUARD_N && !bval) bv = make_float4(0.f, 0.f, 0.f, 0.f);
        __syncthreads();
        As[lcol + 0][lrow] = av.x; As[lcol + 1][lrow] = av.y;
        As[lcol + 2][lrow] = av.z; As[lcol + 3][lrow] = av.w;
        Bs[lcol + 0][lrow] = bv.x; Bs[lcol + 1][lrow] = bv.y;
        Bs[lcol + 2][lrow] = bv.z; Bs[lcol + 3][lrow] = bv.w;
        __syncthreads();
#pragma unroll
        for (int kk = 0; kk < 8; kk++) {
            float a[8], b[8];
            float4 t;
            t = *reinterpret_cast<const float4*>(&As[kk][ty * 4]);
            a[0] = t.x; a[1] = t.y; a[2] = t.z; a[3] = t.w;
            t = *reinterpret_cast<const float4*>(&As[kk][ty * 4 + 64]);
            a[4] = t.x; a[5] = t.y; a[6] = t.z; a[7] = t.w;
            t = *reinterpret_cast<const float4*>(&Bs[kk][tx * 4]);
            b[0] = t.x; b[1] = t.y; b[2] = t.z; b[3] = t.w;
            t = *reinterpret_cast<const float4*>(&Bs[kk][tx * 4 + 64]);
            b[4] = t.x; b[5] = t.y; b[6] = t.z; b[7] = t.w;
#pragma unroll
            for (int i = 0; i < 8; i++)
#pragma unroll
                for (int j = 0; j < 8; j++)
                    acc[i][j] = fmaf(a[i], b[j], acc[i][j]);
        }
    }

#pragma unroll
    for (int ih = 0; ih < 2; ih++) {
#pragma unroll
        for (int ii = 0; ii < 4; ii++) {
            int i = ih * 4 + ii;
            int m = m0 + ih * 64 + ty * 4 + ii;
#pragma unroll
            for (int jh = 0; jh < 2; jh++) {
                int n = n0 + jh * 64 + tx * 4;
                if (GUARD_N && n >= N) continue;
                float4 v;
                v.x = acc[i][jh * 4 + 0]; v.y = acc[i][jh * 4 + 1];
                v.z = acc[i][jh * 4 + 2]; v.w = acc[i][jh * 4 + 3];
                if (RES) {
                    float4 rv = *reinterpret_cast<const float4*>(Res + (size_t)m * N + n);
                    v.x += rv.x; v.y += rv.y; v.z += rv.z; v.w += rv.w;
                }
                *reinterpret_cast<float4*>(C + (size_t)m * N + n) = v;
            }
        }
    }
}

__global__ __launch_bounds__(256, 2)
void gemm1_fix(const float* __restrict__ W) {
    if (g_flag1 == 0) return;
    sgemm_f32_body<true, false>(g_u, W, nullptr, g_zx, DPROJ, DM);
}
__global__ __launch_bounds__(256, 2)
void gemm2_fix(const float* __restrict__ W, const float* __restrict__ Res,
               float* __restrict__ out) {
    if (g_flag2 == 0) return;
    sgemm_f32_body<false, true>(g_y, W, Res, out, DM, DIN);
}

// ---------------------------------------------------------------------------
// Exact fp32 dt: dtraw[t,h] = u[t,:] . W[8320+h,:], softplus + dA.
// ---------------------------------------------------------------------------
#define DTTOK 4
__global__ __launch_bounds__(256)
void dtexact_kernel(const float* __restrict__ W,
                    const float* __restrict__ dt_bias,
                    const float* __restrict__ A_log) {
    __shared__ float su[DTTOK][DM];
    int t0 = blockIdx.x * DTTOK;
    int tid = threadIdx.x, lane = tid & 31, wid = tid >> 5;
    for (int i = tid; i < DTTOK * DM; i += 256) {
        int tt = i >> 11, k = i & (DM - 1);
        su[tt][k] = g_u[(size_t)(t0 + tt) * DM + k];
    }
    __syncthreads();
    const float* Wdt = W + (size_t)(DPROJ - NH) * DM;
    for (int hb = 0; hb < 8; hb++) {
        int h = hb * 8 + wid;
        const float* wr = Wdt + (size_t)h * DM;
        float wreg[64];
#pragma unroll
        for (int i = 0; i < 64; i++) wreg[i] = wr[lane + 32 * i];
#pragma unroll
        for (int tt = 0; tt < DTTOK; tt++) {
            float acc = 0.f;
#pragma unroll
            for (int i = 0; i < 64; i++)
                acc = fmaf(wreg[i], su[tt][lane + 32 * i], acc);
#pragma unroll
            for (int o = 16; o; o >>= 1)
                acc += __shfl_xor_sync(0xffffffffu, acc, o);
            if (lane == 0) {
                float raw = acc + dt_bias[h];
                float dtv = (raw > 20.f) ? raw : log1pf(expf(raw));
                float Av = -expf(A_log[h]);
                int r = t0 + tt;
                g_dt[r * NH + h] = dtv;
                g_dA[r * NH + h] = expf(dtv * Av);
            }
        }
    }
}

// ---------------------------------------------------------------------------
// Depthwise causal conv (k=4) + SiLU.
// ---------------------------------------------------------------------------
#define CCH 32
__global__ void conv_kernel(const float* __restrict__ cw,
                            const float* __restrict__ cb) {
    int c = blockIdx.x * blockDim.x + threadIdx.x;
    if (c >= DCONV) return;
    int b = blockIdx.y >> 5;
    int chunk = blockIdx.y & 31;
    int t0 = chunk * CCH;
    float w0 = cw[c * 4 + 0], w1 = cw[c * 4 + 1];
    float w2 = cw[c * 4 + 2], w3 = cw[c * 4 + 3];
    float bias = cb[c];
    const float* src = g_zx + (size_t)b * T_ * DPROJ + DIN + c;
    float* dst = g_xbc + (size_t)b * T_ * DCONV + c;
    float x0 = (t0 >= 3) ? src[(size_t)(t0 - 3) * DPROJ] : 0.f;
    float x1 = (t0 >= 2) ? src[(size_t)(t0 - 2) * DPROJ] : 0.f;
    float x2 = (t0 >= 1) ? src[(size_t)(t0 - 1) * DPROJ] : 0.f;
    for (int t = t0; t < t0 + CCH; t++) {
        float x3 = src[(size_t)t * DPROJ];
        float v = bias + x0 * w0 + x1 * w1 + x2 * w2 + x3 * w3;
        v = v * sigmoidf_(v);
        dst[(size_t)t * DCONV] = v;
        x0 = x1; x1 = x2; x2 = x3;
    }
}

// ---------------------------------------------------------------------------
// Sequential selective scan (FFMA2, 4-way split accumulator).
// ---------------------------------------------------------------------------
__global__ __launch_bounds__(64)
void scan_kernel(const float* __restrict__ Dvec) {
    int bh = blockIdx.x;
    int b = bh >> 6, hh = bh & 63;
    int p = threadIdx.x;

    __shared__ __align__(16) float sB[2][64];
    __shared__ __align__(16) float sC[2][64];
    __shared__ __align__(16) float sX[2][64];
    __shared__ float sS[2][2];

    unsigned long long st2[32];
#pragma unroll
    for (int n = 0; n < 32; n++) st2[n] = 0ull;
    float Dh = Dvec[hh];

    const size_t base = (size_t)b * T_ * DCONV;
    {
        sX[0][p] = g_xbc[base + hh * 64 + p];
        sB[0][p] = g_xbc[base + 4096 + p];
        sC[0][p] = g_xbc[base + 4160 + p];
        if (p < 2) {
            int rr = b * T_;
            sS[0][p] = (p == 0) ? g_dA[rr * NH + hh] : g_dt[rr * NH + hh];
        }
    }

    for (int t = 0; t < T_; t++) {
        int buf = t & 1;
        __syncthreads();
        if (t + 1 < T_) {
            size_t rq = base + (size_t)(t + 1) * DCONV;
            sX[buf ^ 1][p] = g_xbc[rq + hh * 64 + p];
            sB[buf ^ 1][p] = g_xbc[rq + 4096 + p];
            sC[buf ^ 1][p] = g_xbc[rq + 4160 + p];
            if (p < 2) {
                int rr = b * T_ + t + 1;
                sS[buf ^ 1][p] = (p == 0) ? g_dA[rr * NH + hh] : g_dt[rr * NH + hh];
            }
        }
        float dAv = sS[buf][0];
        float dtx = sS[buf][1] * sX[buf][p];
        unsigned long long dA2  = packdup(dAv);
        unsigned long long dtx2 = packdup(dtx);
        unsigned long long a4[4] = {0ull, 0ull, 0ull, 0ull};
#pragma unroll
        for (int q = 0; q < 16; q++) {
            ulonglong2 b2 = *reinterpret_cast<const ulonglong2*>(&sB[buf][q * 4]);
            ulonglong2 c2 = *reinterpret_cast<const ulonglong2*>(&sC[buf][q * 4]);
            unsigned long long t0, t1;
            MULF2(t0, dtx2, b2.x);
            MULF2(t1, dtx2, b2.y);
            FMAF2(st2[q * 2 + 0], st2[q * 2 + 0], dA2, t0);
            FMAF2(st2[q * 2 + 1], st2[q * 2 + 1], dA2, t1);
            FMAF2(a4[(2 * q) & 3], st2[q * 2 + 0], c2.x, a4[(2 * q) & 3]);
            FMAF2(a4[(2 * q + 1) & 3], st2[q * 2 + 1], c2.y, a4[(2 * q + 1) & 3]);
        }
        float2 p0 = unpack2(a4[0]), p1 = unpack2(a4[1]);
        float2 p2 = unpack2(a4[2]), p3 = unpack2(a4[3]);
        float accs = ((p0.x + p0.y) + (p1.x + p1.y)) + ((p2.x + p2.y) + (p3.x + p3.y));
        g_y[(size_t)(b * T_ + t) * DIN + hh * 64 + p] = accs + Dh * sX[buf][p];
    }
}

// ---------------------------------------------------------------------------
// y = y * silu(z); RMSNorm * norm_w; emit fp32 + fp16. Block per token.
// ---------------------------------------------------------------------------
__global__ void gate_rms_kernel(const float* __restrict__ norm_w) {
    int r = blockIdx.x;
    float ss = 0.f;
    for (int i = threadIdx.x; i < DIN; i += blockDim.x) {
        float zv = g_zx[(size_t)r * DPROJ + i];
        float g = g_y[(size_t)r * DIN + i] * zv * sigmoidf_(zv);
        g_y[(size_t)r * DIN + i] = g;
        ss += g * g;
    }
    __shared__ float sh[32];
    int lane = threadIdx.x & 31, wid = threadIdx.x >> 5;
#pragma unroll
    for (int o = 16; o; o >>= 1) ss += __shfl_xor_sync(0xffffffffu, ss, o);
    if (lane == 0) sh[wid] = ss;
    __syncthreads();
    __shared__ float sc;
    if (threadIdx.x == 0) {
        float tot = 0.f;
        int nw = blockDim.x >> 5;
        for (int i = 0; i < nw; i++) tot += sh[i];
        sc = rsqrtf(tot / DIN + 1e-5f);
    }
    __syncthreads();
    float s = sc;
    for (int i = threadIdx.x; i < DIN; i += blockDim.x) {
        size_t idx = (size_t)r * DIN + i;
        float v = g_y[idx] * s * norm_w[i];
        g_y[idx]  = v;
        g_yh[idx] = __float2half_rn(v);
    }
}

// ---------------------------------------------------------------------------
// launch
// ---------------------------------------------------------------------------
extern "C" void kernel_launch(void* const* d_in, const int* in_sizes, int n_in,
                              void* d_out, int out_size) {
    const float* x          = (const float*)d_in[0];
    const float* ln_w       = (const float*)d_in[1];
    const float* ln_b       = (const float*)d_in[2];
    const float* in_proj_w  = (const float*)d_in[3];
    const float* conv_w     = (const float*)d_in[4];
    const float* conv_b     = (const float*)d_in[5];
    const float* dt_bias    = (const float*)d_in[6];
    const float* A_log      = (const float*)d_in[7];
    const float* Dv         = (const float*)d_in[8];
    const float* norm_w     = (const float*)d_in[9];
    const float* out_proj_w = (const float*)d_in[10];
    float* out = (float*)d_out;

    {
        int n1 = DPROJ * DM / 4, n2 = DM * DIN / 4;
        wcvt_kernel<<<(n1 + 255) / 256, 256>>>(in_proj_w, g_w1h, n1);
        wcvt_kernel<<<(n2 + 255) / 256, 256>>>(out_proj_w, g_w2h, n2);
    }

    ln_kernel<<<NTOK, 256>>>(x, ln_w, ln_b);
    dtexact_kernel<<<NTOK / DTTOK, 256>>>(in_proj_w, dt_bias, A_log);

    preclear1_kernel<<<1, 64>>>();
    gemm1_f16<<<dim3((DPROJ + 127) / 128, NTOK / 128), 256>>>();
    probe1_kernel<<<NPROBE, 256>>>(in_proj_w);
    gemm1_fix<<<dim3((DPROJ + 127) / 128, NTOK / 128), 256>>>(in_proj_w);

    conv_kernel<<<dim3((DCONV + 255) / 256, B_ * 32), 256>>>(conv_w, conv_b);
    scan_kernel<<<B_ * NH, 64>>>(Dv);
    gate_rms_kernel<<<NTOK, 256>>>(norm_w);

    preclear2_kernel<<<1, 64>>>(out);
    gemm2_f16<<<dim3(DM / 128, NTOK / 128), 256>>>(x, out);
    probe2_kernel<<<NPROBE, 256>>>(x, out_proj_w, out);
    gemm2_fix<<<dim3(DM / 128, NTOK / 128), 256>>>(out_proj_w, x, out);
}

// round 14
// speedup vs baseline: 1.7479x; 1.7479x over previous
#include <cuda_runtime.h>
#include <math.h>
#include <stdint.h>

// ---------------------------------------------------------------------------
// Mamba2 block, B=2, T=1024, D_MODEL=2048, D_STATE=64, HEADDIM=64
// R13: fp32 pipeline at the FFMA roofline (all matrix units proven dead on
// this target). Deltas vs best (R8, 3190us):
//   - scan: 4-deep cp.async prefetch ring (was L2-latency-bound at ~280cy/step)
//   - GEMM: explicit register double-buffering of global loads (deterministic
//     LDG/compute overlap instead of relying on cross-warp interleave)
// ---------------------------------------------------------------------------

#define B_     2
#define T_     1024
#define DM     2048
#define DIN    4096
#define DCONV  4224
#define DPROJ  8384
#define NH     64
#define NTOK   (B_ * T_)   // 2048

__device__ float g_u  [(size_t)NTOK * DM];
__device__ float g_zx [(size_t)NTOK * DPROJ];
__device__ float g_xbc[(size_t)NTOK * DCONV];
__device__ float g_dt [(size_t)NTOK * NH];
__device__ float g_dA [(size_t)NTOK * NH];
__device__ float g_y  [(size_t)NTOK * DIN];

__device__ __forceinline__ float sigmoidf_(float v) { return 1.f / (1.f + expf(-v)); }

// ---- packed f32x2 helpers (FFMA2) -----------------------------------------
#define FMAF2(d, a, b, c) \
    asm("fma.rn.f32x2 %0, %1, %2, %3;" : "=l"(d) : "l"(a), "l"(b), "l"(c))
#define MULF2(d, a, b) \
    asm("mul.rn.f32x2 %0, %1, %2;" : "=l"(d) : "l"(a), "l"(b))
__device__ __forceinline__ unsigned long long packdup(float x) {
    unsigned long long r;
    uint32_t xi = __float_as_uint(x);
    asm("mov.b64 %0, {%1,%1};" : "=l"(r) : "r"(xi));
    return r;
}
__device__ __forceinline__ float2 unpack2(unsigned long long v) {
    uint32_t lo, hi;
    asm("mov.b64 {%0,%1}, %2;" : "=r"(lo), "=r"(hi) : "l"(v));
    return make_float2(__uint_as_float(lo), __uint_as_float(hi));
}

// ---- cp.async helpers ------------------------------------------------------
__device__ __forceinline__ uint32_t smem_u32(const void* p) {
    return (uint32_t)__cvta_generic_to_shared(p);
}
#define CPA4(dst, src) asm volatile("cp.async.ca.shared.global [%0], [%1], 4;" :: "r"(dst), "l"(src))
#define CPA_COMMIT()   asm volatile("cp.async.commit_group;")
#define CPA_WAIT2()    asm volatile("cp.async.wait_group 2;")

// ---------------------------------------------------------------------------
// LayerNorm: one block per token row (D=2048)
// ---------------------------------------------------------------------------
__global__ void ln_kernel(const float* __restrict__ x,
                          const float* __restrict__ w,
                          const float* __restrict__ bb) {
    int r = blockIdx.x;
    const float* xr = x + (size_t)r * DM;
    float s = 0.f, s2 = 0.f;
    for (int i = threadIdx.x; i < DM; i += blockDim.x) {
        float v = xr[i]; s += v; s2 += v * v;
    }
    __shared__ float shs[32], shs2[32];
    int lane = threadIdx.x & 31, wid = threadIdx.x >> 5;
#pragma unroll
    for (int o = 16; o; o >>= 1) {
        s  += __shfl_xor_sync(0xffffffffu, s, o);
        s2 += __shfl_xor_sync(0xffffffffu, s2, o);
    }
    if (lane == 0) { shs[wid] = s; shs2[wid] = s2; }
    __syncthreads();
    __shared__ float mu_s, inv_s;
    if (threadIdx.x == 0) {
        float ts = 0.f, ts2 = 0.f;
        int nw = blockDim.x >> 5;
        for (int i = 0; i < nw; i++) { ts += shs[i]; ts2 += shs2[i]; }
        float mu = ts / DM;
        float var = ts2 / DM - mu * mu;
        mu_s = mu;
        inv_s = rsqrtf(var + 1e-5f);
    }
    __syncthreads();
    float mu = mu_s, inv = inv_s;
    for (int i = threadIdx.x; i < DM; i += blockDim.x)
        g_u[(size_t)r * DM + i] = (xr[i] - mu) * inv * w[i] + bb[i];
}

// ---------------------------------------------------------------------------
// SGEMM NT with FFMA2 + explicit register double-buffering of global loads.
// C[m,n] = sum_k A[m,k] * Bw[n,k] (+Res[m,n]); 128x128x8 tile, 256 threads,
// 8x8 microtile (acc as 8x4 f32x2 pairs).
// ---------------------------------------------------------------------------
template<bool GUARD_N, bool RES>
__device__ __forceinline__ void sgemm_body(const float* __restrict__ A,
                                           const float* __restrict__ Bw,
                                           const float* __restrict__ Res,
                                           float* __restrict__ C,
                                           int M, int N, int K) {
    __shared__ __align__(16) float As[8][128];
    __shared__ __align__(16) float Bs[8][128];

    const int tid = threadIdx.x;
    const int m0 = blockIdx.y * 128;
    const int n0 = blockIdx.x * 128;

    const int lrow = tid >> 1;
    const int lcol = (tid & 1) << 2;

    const int tx = tid & 15;
    const int ty = tid >> 4;

    unsigned long long acc2[8][4];
#pragma unroll
    for (int i = 0; i < 8; i++)
#pragma unroll
        for (int j = 0; j < 4; j++) acc2[i][j] = 0ull;

    int brow = n0 + lrow;
    bool bval = true;
    if (GUARD_N && brow >= N) { brow = 0; bval = false; }

    const float* Ap = A  + (size_t)(m0 + lrow) * K + lcol;
    const float* Bp = Bw + (size_t)brow * K + lcol;

    // prime the register pipe
    float4 av = *reinterpret_cast<const float4*>(Ap);
    float4 bv = *reinterpret_cast<const float4*>(Bp);
    if (GUARD_N && !bval) bv = make_float4(0.f, 0.f, 0.f, 0.f);

    for (int k0 = 0; k0 < K; k0 += 8) {
        __syncthreads();
        As[lcol + 0][lrow] = av.x; As[lcol + 1][lrow] = av.y;
        As[lcol + 2][lrow] = av.z; As[lcol + 3][lrow] = av.w;
        Bs[lcol + 0][lrow] = bv.x; Bs[lcol + 1][lrow] = bv.y;
        Bs[lcol + 2][lrow] = bv.z; Bs[lcol + 3][lrow] = bv.w;
        __syncthreads();

        // issue next-slice loads; latency overlaps with the compute below
        if (k0 + 8 < K) {
            av = *reinterpret_cast<const float4*>(Ap + k0 + 8);
            bv = *reinterpret_cast<const float4*>(Bp + k0 + 8);
            if (GUARD_N && !bval) bv = make_float4(0.f, 0.f, 0.f, 0.f);
        }

#pragma unroll
        for (int kk = 0; kk < 8; kk++) {
            float a[8];
            float4 t;
            t = *reinterpret_cast<const float4*>(&As[kk][ty * 4]);
            a[0] = t.x; a[1] = t.y; a[2] = t.z; a[3] = t.w;
            t = *reinterpret_cast<const float4*>(&As[kk][ty * 4 + 64]);
            a[4] = t.x; a[5] = t.y; a[6] = t.z; a[7] = t.w;
            ulonglong2 bv0 = *reinterpret_cast<const ulonglong2*>(&Bs[kk][tx * 4]);
            ulonglong2 bv1 = *reinterpret_cast<const ulonglong2*>(&Bs[kk][tx * 4 + 64]);
            unsigned long long b0 = bv0.x, b1 = bv0.y, b2 = bv1.x, b3 = bv1.y;
#pragma unroll
            for (int i = 0; i < 8; i++) {
                unsigned long long a2 = packdup(a[i]);
                FMAF2(acc2[i][0], a2, b0, acc2[i][0]);
                FMAF2(acc2[i][1], a2, b1, acc2[i][1]);
                FMAF2(acc2[i][2], a2, b2, acc2[i][2]);
                FMAF2(acc2[i][3], a2, b3, acc2[i][3]);
            }
        }
    }

#pragma unroll
    for (int ih = 0; ih < 2; ih++) {
#pragma unroll
        for (int ii = 0; ii < 4; ii++) {
            int i = ih * 4 + ii;
            int m = m0 + ih * 64 + ty * 4 + ii;
#pragma unroll
            for (int jh = 0; jh < 2; jh++) {
                int n = n0 + jh * 64 + tx * 4;
                if (GUARD_N && n >= N) continue;   // N % 4 == 0, full float4 valid
                float2 p0 = unpack2(acc2[i][jh * 2 + 0]);
                float2 p1 = unpack2(acc2[i][jh * 2 + 1]);
                float4 v = make_float4(p0.x, p0.y, p1.x, p1.y);
                if (RES) {
                    float4 rv = *reinterpret_cast<const float4*>(Res + (size_t)m * N + n);
                    v.x += rv.x; v.y += rv.y; v.z += rv.z; v.w += rv.w;
                }
                *reinterpret_cast<float4*>(C + (size_t)m * N + n) = v;
            }
        }
    }
}

__global__ __launch_bounds__(256, 2)
void gemm1_kernel(const float* __restrict__ W) {
    sgemm_body<true, false>(g_u, W, nullptr, g_zx, NTOK, DPROJ, DM);
}

__global__ __launch_bounds__(256, 2)
void gemm2_kernel(const float* __restrict__ W,
                  const float* __restrict__ Res,
                  float* __restrict__ C) {
    sgemm_body<false, true>(g_y, W, Res, C, NTOK, DM, DIN);
}

// ---------------------------------------------------------------------------
// Depthwise causal conv (k=4) + SiLU. 32 t-chunks per batch.
// ---------------------------------------------------------------------------
#define CCH 32
__global__ void conv_kernel(const float* __restrict__ cw,
                            const float* __restrict__ cb) {
    int c = blockIdx.x * blockDim.x + threadIdx.x;
    if (c >= DCONV) return;
    int b = blockIdx.y >> 5;
    int chunk = blockIdx.y & 31;
    int t0 = chunk * CCH;
    float w0 = cw[c * 4 + 0], w1 = cw[c * 4 + 1];
    float w2 = cw[c * 4 + 2], w3 = cw[c * 4 + 3];
    float bias = cb[c];
    const float* src = g_zx + (size_t)b * T_ * DPROJ + DIN + c;
    float* dst = g_xbc + (size_t)b * T_ * DCONV + c;
    float x0 = (t0 >= 3) ? src[(size_t)(t0 - 3) * DPROJ] : 0.f;
    float x1 = (t0 >= 2) ? src[(size_t)(t0 - 2) * DPROJ] : 0.f;
    float x2 = (t0 >= 1) ? src[(size_t)(t0 - 1) * DPROJ] : 0.f;
    for (int t = t0; t < t0 + CCH; t++) {
        float x3 = src[(size_t)t * DPROJ];
        float v = bias + x0 * w0 + x1 * w1 + x2 * w2 + x3 * w3;
        v = v * sigmoidf_(v);
        dst[(size_t)t * DCONV] = v;
        x0 = x1; x1 = x2; x2 = x3;
    }
}

// ---------------------------------------------------------------------------
// dt = softplus(dt_raw + dt_bias), dA = exp(dt * -exp(A_log))
// ---------------------------------------------------------------------------
__global__ void dt_kernel(const float* __restrict__ dt_bias,
                          const float* __restrict__ A_log) {
    int r = blockIdx.x;
    int h = threadIdx.x;   // 64
    float raw = g_zx[(size_t)r * DPROJ + DIN + DCONV + h] + dt_bias[h];
    float dtv = (raw > 20.f) ? raw : log1pf(expf(raw));
    float Av = -expf(A_log[h]);
    g_dt[r * NH + h] = dtv;
    g_dA[r * NH + h] = expf(dtv * Av);
}

// ---------------------------------------------------------------------------
// Sequential selective scan, FFMA2 core, 4-deep cp.async prefetch ring.
// Block = (b, head), 64 threads (thread = p). Per step: wait_group(2) ->
// barrier -> prefetch t+3 into the buffer freed by step t-1 -> compute.
// Accounting: before iter t, pending groups = {t, t+1, t+2}; wait<=2 => t done.
// ---------------------------------------------------------------------------
__global__ __launch_bounds__(64)
void scan_kernel(const float* __restrict__ Dvec) {
    int bh = blockIdx.x;
    int b = bh >> 6, hh = bh & 63;
    int p = threadIdx.x;

    __shared__ __align__(16) float sB[4][64];
    __shared__ __align__(16) float sC[4][64];
    __shared__ __align__(16) float sX[4][64];
    __shared__ __align__(8)  float sS[4][2];   // [buf][0]=dA, [buf][1]=dt

    unsigned long long st2[32];
#pragma unroll
    for (int n = 0; n < 32; n++) st2[n] = 0ull;
    float Dh = Dvec[hh];

    const size_t base = (size_t)b * T_ * DCONV;
    const int rr0 = b * T_;

    auto prefetch = [&](int t) {
        size_t rq = base + (size_t)t * DCONV;
        int bf = t & 3;
        CPA4(smem_u32(&sX[bf][p]), g_xbc + rq + hh * 64 + p);
        CPA4(smem_u32(&sB[bf][p]), g_xbc + rq + 4096 + p);
        CPA4(smem_u32(&sC[bf][p]), g_xbc + rq + 4160 + p);
        if (p < 2) {
            const float* sp = (p == 0) ? (g_dA + (rr0 + t) * NH + hh)
                                       : (g_dt + (rr0 + t) * NH + hh);
            CPA4(smem_u32(&sS[bf][p]), sp);
        }
    };

    // warmup: groups for t = 0,1,2
    prefetch(0); CPA_COMMIT();
    prefetch(1); CPA_COMMIT();
    prefetch(2); CPA_COMMIT();

    for (int t = 0; t < T_; t++) {
        int bf = t & 3;
        CPA_WAIT2();          // group t complete (per-thread)
        __syncthreads();      // cross-thread visibility; step t-1 compute done
        if (t + 3 < T_) prefetch(t + 3);
        CPA_COMMIT();         // commit every iter (possibly empty) to keep count

        float dAv = sS[bf][0];
        float dtx = sS[bf][1] * sX[bf][p];
        unsigned long long dA2  = packdup(dAv);
        unsigned long long dtx2 = packdup(dtx);
        unsigned long long a4[4] = {0ull, 0ull, 0ull, 0ull};
#pragma unroll
        for (int q = 0; q < 16; q++) {
            ulonglong2 b2 = *reinterpret_cast<const ulonglong2*>(&sB[bf][q * 4]);
            ulonglong2 c2 = *reinterpret_cast<const ulonglong2*>(&sC[bf][q * 4]);
            unsigned long long t0, t1;
            MULF2(t0, dtx2, b2.x);
            MULF2(t1, dtx2, b2.y);
            FMAF2(st2[q * 2 + 0], st2[q * 2 + 0], dA2, t0);
            FMAF2(st2[q * 2 + 1], st2[q * 2 + 1], dA2, t1);
            FMAF2(a4[(2 * q) & 3], st2[q * 2 + 0], c2.x, a4[(2 * q) & 3]);
            FMAF2(a4[(2 * q + 1) & 3], st2[q * 2 + 1], c2.y, a4[(2 * q + 1) & 3]);
        }
        float2 p0 = unpack2(a4[0]), p1 = unpack2(a4[1]);
        float2 p2 = unpack2(a4[2]), p3 = unpack2(a4[3]);
        float accs = ((p0.x + p0.y) + (p1.x + p1.y)) + ((p2.x + p2.y) + (p3.x + p3.y));
        g_y[(size_t)(b * T_ + t) * DIN + hh * 64 + p] = accs + Dh * sX[bf][p];
    }
}

// ---------------------------------------------------------------------------
// y = y * silu(z); y = y * rsqrt(mean(y^2)+eps) * norm_w. Block per token.
// ---------------------------------------------------------------------------
__global__ void gate_rms_kernel(const float* __restrict__ norm_w) {
    int r = blockIdx.x;
    float ss = 0.f;
    for (int i = threadIdx.x; i < DIN; i += blockDim.x) {
        float zv = g_zx[(size_t)r * DPROJ + i];
        float g = g_y[(size_t)r * DIN + i] * zv * sigmoidf_(zv);
        g_y[(size_t)r * DIN + i] = g;
        ss += g * g;
    }
    __shared__ float sh[32];
    int lane = threadIdx.x & 31, wid = threadIdx.x >> 5;
#pragma unroll
    for (int o = 16; o; o >>= 1) ss += __shfl_xor_sync(0xffffffffu, ss, o);
    if (lane == 0) sh[wid] = ss;
    __syncthreads();
    __shared__ float sc;
    if (threadIdx.x == 0) {
        float tot = 0.f;
        int nw = blockDim.x >> 5;
        for (int i = 0; i < nw; i++) tot += sh[i];
        sc = rsqrtf(tot / DIN + 1e-5f);
    }
    __syncthreads();
    float s = sc;
    for (int i = threadIdx.x; i < DIN; i += blockDim.x)
        g_y[(size_t)r * DIN + i] *= s * norm_w[i];
}

// ---------------------------------------------------------------------------
// launch
// ---------------------------------------------------------------------------
extern "C" void kernel_launch(void* const* d_in, const int* in_sizes, int n_in,
                              void* d_out, int out_size) {
    const float* x          = (const float*)d_in[0];
    const float* ln_w       = (const float*)d_in[1];
    const float* ln_b       = (const float*)d_in[2];
    const float* in_proj_w  = (const float*)d_in[3];
    const float* conv_w     = (const float*)d_in[4];
    const float* conv_b     = (const float*)d_in[5];
    const float* dt_bias    = (const float*)d_in[6];
    const float* A_log      = (const float*)d_in[7];
    const float* Dv         = (const float*)d_in[8];
    const float* norm_w     = (const float*)d_in[9];
    const float* out_proj_w = (const float*)d_in[10];
    float* out = (float*)d_out;

    ln_kernel<<<NTOK, 256>>>(x, ln_w, ln_b);
    gemm1_kernel<<<dim3((DPROJ + 127) / 128, NTOK / 128), 256>>>(in_proj_w);
    conv_kernel<<<dim3((DCONV + 255) / 256, B_ * 32), 256>>>(conv_w, conv_b);
    dt_kernel<<<NTOK, NH>>>(dt_bias, A_log);
    scan_kernel<<<B_ * NH, 64>>>(Dv);
    gate_rms_kernel<<<NTOK, 256>>>(norm_w);
    gemm2_kernel<<<dim3(DM / 128, NTOK / 128), 256>>>(out_proj_w, x, out);
}